// round 8
// baseline (speedup 1.0000x reference)
#include <cuda_runtime.h>
#include <cstdint>

// Problem constants (fixed by reference setup_inputs)
#define NB  8
#define LSZ 512
#define CC  6
#define NN  (NB * LSZ)       // 4096
#define KK  9
#define NK  (NN * KK)        // 36864
#define HB  256              // half graph (column pairing distance)
#define ROWS_PER_CTA 4

#define GL_PER   (2 * LSZ - 1)
#define SQ_PER   (2 * (LSZ - 2))
#define GL_TOT   (NB * GL_PER)      // 8184
#define SQ_TOT   (NB * SQ_PER)      // 8160
#define EDGE_TOT (2 * GL_TOT + 2 * SQ_TOT)   // 32688
#define EDGE_BLOCKS ((EDGE_TOT + 255) / 256) // 128

typedef unsigned long long u64;

// Interleaved paired SoA per channel c, per (graph b, q in [0,256)):
//   g_q1[c][b*HB+q] = (x_lo, x_hi, y_lo, y_hi)
//   g_q2[c][b*HB+q] = (z_lo, z_hi, w_lo, w_hi)
// lo = node b*512+q, hi = node b*512+q+256.
// w = |x|^2, or 1e30 sentinel if channel padded OR node is BOS/global.
__device__ float4 g_q1[CC][NB * HB];
__device__ float4 g_q2[CC][NB * HB];
__device__ int    g_info[NN];   // bits 0..5: pad mask; bit 6: BOS/global

// ---- packed f32x2 helpers (each half rounds identically to scalar op) ----
__device__ __forceinline__ u64 pack2(float lo, float hi) {
    u64 r; asm("mov.b64 %0, {%1, %2};" : "=l"(r) : "f"(lo), "f"(hi)); return r;
}
__device__ __forceinline__ void unpack2(u64 v, float& lo, float& hi) {
    asm("mov.b64 {%0, %1}, %2;" : "=f"(lo), "=f"(hi) : "l"(v));
}
__device__ __forceinline__ u64 mul2(u64 a, u64 b) {
    u64 d; asm("mul.rn.f32x2 %0, %1, %2;" : "=l"(d) : "l"(a), "l"(b)); return d;
}
__device__ __forceinline__ u64 add2(u64 a, u64 b) {
    u64 d; asm("add.rn.f32x2 %0, %1, %2;" : "=l"(d) : "l"(a), "l"(b)); return d;
}
__device__ __forceinline__ u64 fma2(u64 a, u64 b, u64 c) {
    u64 d; asm("fma.rn.f32x2 %0, %1, %2, %3;" : "=l"(d) : "l"(a), "l"(b), "l"(c)); return d;
}

// ---------------------------------------------------------------------------
// Kernel 1: prep (interleaved paired SoA + masks) merged with edge lists
// ---------------------------------------------------------------------------
__global__ void __launch_bounds__(256)
prep_edges_kernel(const float* __restrict__ X,
                  const int* __restrict__ AP,
                  const int* __restrict__ S,
                  float* __restrict__ out) {
    const int tid = threadIdx.x;
    if (blockIdx.x < NB) {
        const int b = blockIdx.x;
        const int q = tid;
        float ax[2][CC], ay[2][CC], az[2][CC], aw[2][CC];
#pragma unroll
        for (int h = 0; h < 2; h++) {
            const int i = b * LSZ + h * HB + q;
            const bool bos = (S[i] == 0);
            int mask = bos ? 64 : 0;
#pragma unroll
            for (int c = 0; c < CC; c++) {
                float x = X[(i * CC + c) * 3 + 0];
                float y = X[(i * CC + c) * 3 + 1];
                float z = X[(i * CC + c) * 3 + 2];
                float sq = x * x + y * y + z * z;
                bool pad = (AP[i * CC + c] == 0);
                if (pad) mask |= (1 << c);
                ax[h][c] = x; ay[h][c] = y; az[h][c] = z;
                aw[h][c] = (pad || bos) ? 1e30f : sq;
            }
            g_info[i] = mask;
        }
#pragma unroll
        for (int c = 0; c < CC; c++) {
            g_q1[c][b * HB + q] = make_float4(ax[0][c], ax[1][c], ay[0][c], ay[1][c]);
            g_q2[c][b * HB + q] = make_float4(az[0][c], az[1][c], aw[0][c], aw[1][c]);
        }
    } else {
        const int t = (blockIdx.x - NB) * 256 + tid;
        if (t >= EDGE_TOT) return;
        int val;
        if (t < 2 * GL_TOT) {
            int r = t / GL_TOT, u = t % GL_TOT;
            int b = u / GL_PER, q = u % GL_PER;
            if (r == 0) val = (q < LSZ) ? 0 : (q - (LSZ - 1));
            else        val = (q < LSZ) ? q : 0;
            val += b * LSZ;
        } else {
            int t2 = t - 2 * GL_TOT;
            int r = t2 / SQ_TOT, u = t2 % SQ_TOT;
            int b = u / SQ_PER, q = u % SQ_PER;
            if (r == 0) val = (q < LSZ - 2) ? (q + 1) : (q - (LSZ - 2) + 2);
            else        val = (q < LSZ - 2) ? (q + 2) : (q - (LSZ - 2) + 1);
            val += b * LSZ;
        }
        out[4 * NK + t] = (float)val;
    }
}

// ---------------------------------------------------------------------------
// Kernel 2: 4 rows per CTA (single wave). Per row: bit-exact masked min-pair
// distance + top-9 with exact lower-index tie-break via REDUX.MIN.
// 128 threads; thread t owns columns t, t+128, t+256, t+384 (ascending for
// stable tie order), computed as two packed f32x2 column pairs.
// ---------------------------------------------------------------------------
__global__ void __launch_bounds__(128)
knn_kernel(const int* __restrict__ sec, float* __restrict__ out) {
    const int tid  = threadIdx.x;
    const int wid  = tid >> 5;
    const int row0 = blockIdx.x * ROWS_PER_CTA;
    const int b    = row0 >> 9;           // all 4 rows share one graph (512%4==0)
    const int base = b * HB;
    const float INF = __int_as_float(0x7f800000);

    __shared__ u64 wOut[4 * KK];

#pragma unroll 1
    for (int rr = 0; rr < ROWS_PER_CTA; rr++) {
        const int i = row0 + rr;
        const int infoI = g_info[i];      // uniform per row

        // BOS/global row: dist row is all 1e10 -> dknn=1e10, valid=0, dst=-1.
        if (infoI & 64) {
            if (tid < KK) {
                out[0 * NK + i * KK + tid] = 1e10f;
                out[1 * NK + i * KK + tid] = (float)i;
                out[2 * NK + i * KK + tid] = -1.0f;
                out[3 * NK + i * KK + tid] = 0.0f;
            }
            continue;                     // CTA-uniform, no barrier inside
        }

        const int li  = i & (LSZ - 1);
        const int qi  = li & (HB - 1);
        const int hi_ = li >> 8;          // which half of the pair holds row i

        // per-thread candidates in ascending column order
        float d0, d1, d2, d3;
        int   jl0 = tid, jl1 = tid + 128, jl2 = tid + 256, jl3 = tid + 384;

        if ((infoI & 63) != 63) {
            // -------------- fast path: row has >=1 valid channel --------------
            u64 ax2[CC], ay2[CC], az2[CC], aw2[CC];
#pragma unroll
            for (int c = 0; c < CC; c++) {
                float4 q1 = g_q1[c][base + qi];
                float4 q2 = g_q2[c][base + qi];
                float x = hi_ ? q1.y : q1.x;
                float y = hi_ ? q1.w : q1.z;
                float z = hi_ ? q2.y : q2.x;
                float w = hi_ ? q2.w : q2.z;
                ax2[c] = pack2(x, x);
                ay2[c] = pack2(y, y);
                az2[c] = pack2(z, z);
                aw2[c] = pack2(w, w);
            }
            const u64 neg2 = pack2(-2.0f, -2.0f);

#pragma unroll
            for (int p = 0; p < 2; p++) {
                const int q = tid + p * 128;
                float mlo = 3.4e38f, mhi = 3.4e38f;
#pragma unroll
                for (int d = 0; d < CC; d++) {
                    ulonglong2 vA = *reinterpret_cast<const ulonglong2*>(&g_q1[d][base + q]);
                    ulonglong2 vB = *reinterpret_cast<const ulonglong2*>(&g_q2[d][base + q]);
                    const u64 bx2 = vA.x, by2 = vA.y, bz2 = vB.x, bw2 = vB.y;
#pragma unroll
                    for (int c = 0; c < CC; c++) {
                        // BIT-EXACT chain: dot = fma(ax,bx,fma(ay,by,az*bz));
                        // r = fma(-2, dot, aw+bw)
                        u64 t2 = mul2(az2[c], bz2);
                        t2 = fma2(ay2[c], by2, t2);
                        t2 = fma2(ax2[c], bx2, t2);
                        u64 s2 = add2(aw2[c], bw2);
                        u64 r2 = fma2(neg2, t2, s2);
                        float rl, rh; unpack2(r2, rl, rh);
                        mlo = fminf(mlo, rl);
                        mhi = fminf(mhi, rh);
                    }
                }
                // sqrt & clamp hoisted out of the 36-way min (monotone)
                float dl = sqrtf(fmaxf(mlo, 0.0f));
                float dh = sqrtf(fmaxf(mhi, 0.0f));
                if (p == 0) { d0 = dl; d2 = dh; }   // cols tid, tid+256
                else        { d1 = dl; d3 = dh; }   // cols tid+128, tid+384
            }
        } else {
            // -------------- cold fallback: row has no valid channel -----------
            // dist_j = 1e10 (BOS col) or 1e10 + sqrt(min_all d2); valid=0 always.
            float Ax[CC], Ay[CC], Az[CC], Asq[CC];
#pragma unroll
            for (int c = 0; c < CC; c++) {
                float4 q1 = g_q1[c][base + qi];
                float4 q2 = g_q2[c][base + qi];
                float x = hi_ ? q1.y : q1.x;
                float y = hi_ ? q1.w : q1.z;
                float z = hi_ ? q2.y : q2.x;
                Ax[c] = x; Ay[c] = y; Az[c] = z;
                Asq[c] = x * x + y * y + z * z;
            }
            float dv[4];
#pragma unroll
            for (int t = 0; t < 4; t++) {
                const int jl = tid + t * 128;      // ascending, matches jl0..jl3
                const int q  = jl & (HB - 1);
                const int hh = jl >> 8;
                const int j  = (b << 9) + jl;
                float dist;
                if (g_info[j] & 64) {
                    dist = 1e10f;
                } else {
                    float m = 3.4e38f;
#pragma unroll
                    for (int d = 0; d < CC; d++) {
                        float4 q1 = g_q1[d][base + q];
                        float4 q2 = g_q2[d][base + q];
                        float bx = hh ? q1.y : q1.x;
                        float by = hh ? q1.w : q1.z;
                        float bz = hh ? q2.y : q2.x;
                        float bsq = bx * bx + by * by + bz * bz;
#pragma unroll
                        for (int c = 0; c < CC; c++) {
                            float dot = fmaf(Ax[c], bx, fmaf(Ay[c], by, Az[c] * bz));
                            float r = fmaf(-2.0f, dot, Asq[c] + bsq);
                            m = fminf(m, r);
                        }
                    }
                    dist = 1e10f + sqrtf(fmaxf(m, 0.0f));
                }
                dv[t] = dist;
            }
            d0 = dv[0]; d1 = dv[1]; d2 = dv[2]; d3 = dv[3];
        }

        // stable sort of 4 (dist, jl) candidates (strict >; equal keys never
        // cross, so ties stay in ascending-jl order)
#define CSWAP(da, db, ja, jb) { \
    if (da > db) { float tf = da; da = db; db = tf; int ti = ja; ja = jb; jb = ti; } }
        CSWAP(d0, d1, jl0, jl1) CSWAP(d2, d3, jl2, jl3)
        CSWAP(d0, d2, jl0, jl2) CSWAP(d1, d3, jl1, jl3)
        CSWAP(d1, d2, jl1, jl2)
#undef CSWAP

        // per-warp: 9 rounds of REDUX.MIN warp-min (dist bits order-isomorphic
        // as u32 since dist >= 0) with exact lower-index tie-break.
        for (int r = 0; r < KK; r++) {
            unsigned db = __float_as_uint(d0);
            unsigned m  = __reduce_min_sync(0xFFFFFFFFu, db);
            unsigned cj = __reduce_min_sync(0xFFFFFFFFu,
                                            (db == m) ? (unsigned)jl0 : 0xFFFFFFFFu);
            if (db == m && (unsigned)jl0 == cj) {   // unique owner (jl unique)
                wOut[wid * KK + r] = ((u64)m << 32) | cj;
                // pop head (shift register; no dynamic indexing)
                d0 = d1; jl0 = jl1;
                d1 = d2; jl1 = jl2;
                d2 = d3; jl2 = jl3;
                d3 = INF;
            }
        }
        __syncthreads();

        // parallel rank-merge of 4 sorted 9-lists; ranks < 9 write outputs.
        // u64 keys carry (dist_bits, jl) so cross-warp ties rank by lower jl.
        if (tid < 4 * KK) {
            const u64 key = wOut[tid];
            const int myw = tid / KK;
            int rank = tid - myw * KK;
#pragma unroll
            for (int w = 0; w < 4; w++) {
                if (w == myw) continue;
#pragma unroll
                for (int rq = 0; rq < KK; rq++)
                    rank += (wOut[w * KK + rq] < key);
            }
            if (rank < KK) {
                float dd = __uint_as_float((unsigned)(key >> 32));
                int   jl = (int)(key & 0xFFFFFFFFu);
                int  dst = (b << 9) + jl;
                bool valid = (dd < 1e10f) && (sec[i] == sec[dst]);
                out[0 * NK + i * KK + rank] = dd;
                out[1 * NK + i * KK + rank] = (float)i;
                out[2 * NK + i * KK + rank] = valid ? (float)dst : -1.0f;
                out[3 * NK + i * KK + rank] = valid ? 1.0f : 0.0f;
            }
        }
        __syncthreads();   // protect wOut before next row's selection writes
    }
}

// ---------------------------------------------------------------------------
extern "C" void kernel_launch(void* const* d_in, const int* in_sizes, int n_in,
                              void* d_out, int out_size) {
    const float* X   = (const float*)d_in[0];
    const int*   AP  = (const int*)d_in[1];
    const int*   S   = (const int*)d_in[2];
    const int*   sec = (const int*)d_in[3];
    float* out = (float*)d_out;

    prep_edges_kernel<<<NB + EDGE_BLOCKS, 256>>>(X, AP, S, out);
    knn_kernel<<<NN / ROWS_PER_CTA, 128>>>(sec, out);
}

// round 9
// speedup vs baseline: 1.3186x; 1.3186x over previous
#include <cuda_runtime.h>
#include <cstdint>

// Problem constants (fixed by reference setup_inputs)
#define NB  8
#define LSZ 512
#define CC  6
#define NN  (NB * LSZ)       // 4096
#define KK  9
#define NK  (NN * KK)        // 36864
#define HB  256              // half graph (column pairing distance)

#define GL_PER   (2 * LSZ - 1)
#define SQ_PER   (2 * (LSZ - 2))
#define GL_TOT   (NB * GL_PER)      // 8184
#define SQ_TOT   (NB * SQ_PER)      // 8160
#define EDGE_TOT (2 * GL_TOT + 2 * SQ_TOT)   // 32688
#define EDGE_BLOCKS ((EDGE_TOT + 127) / 128) // 256 CTAs of 128 appended to knn

typedef unsigned long long u64;

// Interleaved paired SoA per channel c, per (graph b, q in [0,256)):
//   g_q1[c][b*HB+q] = (x_lo, x_hi, y_lo, y_hi)
//   g_q2[c][b*HB+q] = (z_lo, z_hi, w_lo, w_hi)
// lo = node b*512+q, hi = node b*512+q+256.
// w = |x|^2, or 1e30 sentinel if channel padded OR node is BOS/global.
__device__ float4 g_q1[CC][NB * HB];
__device__ float4 g_q2[CC][NB * HB];
__device__ int    g_info[NN];   // bits 0..5: pad mask; bit 6: BOS/global

// ---- packed f32x2 helpers (each half rounds identically to scalar op) ----
__device__ __forceinline__ u64 pack2(float lo, float hi) {
    u64 r; asm("mov.b64 %0, {%1, %2};" : "=l"(r) : "f"(lo), "f"(hi)); return r;
}
__device__ __forceinline__ void unpack2(u64 v, float& lo, float& hi) {
    asm("mov.b64 {%0, %1}, %2;" : "=f"(lo), "=f"(hi) : "l"(v));
}
__device__ __forceinline__ u64 mul2(u64 a, u64 b) {
    u64 d; asm("mul.rn.f32x2 %0, %1, %2;" : "=l"(d) : "l"(a), "l"(b)); return d;
}
__device__ __forceinline__ u64 add2(u64 a, u64 b) {
    u64 d; asm("add.rn.f32x2 %0, %1, %2;" : "=l"(d) : "l"(a), "l"(b)); return d;
}
__device__ __forceinline__ u64 fma2(u64 a, u64 b, u64 c) {
    u64 d; asm("fma.rn.f32x2 %0, %1, %2, %3;" : "=l"(d) : "l"(a), "l"(b), "l"(c)); return d;
}

// ---------------------------------------------------------------------------
// Kernel 1: prep only (interleaved paired SoA + masks). 16 CTAs x 128.
// CTA (b, half): handles q in [half*128, half*128+128) of graph b.
// ---------------------------------------------------------------------------
__global__ void __launch_bounds__(128)
prep_kernel(const float* __restrict__ X,
            const int* __restrict__ AP,
            const int* __restrict__ S) {
    const int b = blockIdx.x >> 1;
    const int q = ((blockIdx.x & 1) << 7) + threadIdx.x;   // 0..255
    float ax[2][CC], ay[2][CC], az[2][CC], aw[2][CC];
#pragma unroll
    for (int h = 0; h < 2; h++) {
        const int i = b * LSZ + h * HB + q;
        const bool bos = (S[i] == 0);
        int mask = bos ? 64 : 0;
#pragma unroll
        for (int c = 0; c < CC; c++) {
            float x = X[(i * CC + c) * 3 + 0];
            float y = X[(i * CC + c) * 3 + 1];
            float z = X[(i * CC + c) * 3 + 2];
            float sq = x * x + y * y + z * z;
            bool pad = (AP[i * CC + c] == 0);
            if (pad) mask |= (1 << c);
            ax[h][c] = x; ay[h][c] = y; az[h][c] = z;
            aw[h][c] = (pad || bos) ? 1e30f : sq;
        }
        g_info[i] = mask;
    }
#pragma unroll
    for (int c = 0; c < CC; c++) {
        g_q1[c][b * HB + q] = make_float4(ax[0][c], ax[1][c], ay[0][c], ay[1][c]);
        g_q2[c][b * HB + q] = make_float4(az[0][c], az[1][c], aw[0][c], aw[1][c]);
    }
}

// ---------------------------------------------------------------------------
// Kernel 2: per-row masked min-pair distance (bit-exact) + top-9 with exact
// lower-index tie-break via REDUX.MIN. Blocks >= NN emit the static edge
// lists. One CTA per row; 128 threads; thread t owns columns t, t+128,
// t+256, t+384 (ascending for stable tie order), as two f32x2 column pairs.
// Min accumulation is tree-structured (exactly associative for finite f32).
// ---------------------------------------------------------------------------
__global__ void __launch_bounds__(128)
knn_kernel(const int* __restrict__ sec, float* __restrict__ out) {
    const int tid = threadIdx.x;

    // ---- tail CTAs: static global + sequential edge lists ----
    if (blockIdx.x >= NN) {
        const int t = (blockIdx.x - NN) * 128 + tid;
        if (t >= EDGE_TOT) return;
        int val;
        if (t < 2 * GL_TOT) {
            int r = t / GL_TOT, u = t % GL_TOT;
            int bb = u / GL_PER, q = u % GL_PER;
            if (r == 0) val = (q < LSZ) ? 0 : (q - (LSZ - 1));
            else        val = (q < LSZ) ? q : 0;
            val += bb * LSZ;
        } else {
            int t2 = t - 2 * GL_TOT;
            int r = t2 / SQ_TOT, u = t2 % SQ_TOT;
            int bb = u / SQ_PER, q = u % SQ_PER;
            if (r == 0) val = (q < LSZ - 2) ? (q + 1) : (q - (LSZ - 2) + 2);
            else        val = (q < LSZ - 2) ? (q + 2) : (q - (LSZ - 2) + 1);
            val += bb * LSZ;
        }
        out[4 * NK + t] = (float)val;
        return;
    }

    const int i = blockIdx.x;
    const int b = i >> 9;
    const float INF = __int_as_float(0x7f800000);

    __shared__ u64 wOut[4 * KK];

    const int infoI = g_info[i];

    // BOS/global row: entire dist row is 1e10 -> dknn=1e10, valid=0, dst=-1.
    if (infoI & 64) {
        if (tid < KK) {
            out[0 * NK + i * KK + tid] = 1e10f;
            out[1 * NK + i * KK + tid] = (float)i;
            out[2 * NK + i * KK + tid] = -1.0f;
            out[3 * NK + i * KK + tid] = 0.0f;
        }
        return;
    }

    const int base = b * HB;
    const int li   = i & (LSZ - 1);
    const int qi   = li & (HB - 1);
    const int hi_  = li >> 8;       // which half of the pair holds row i

    // per-thread candidates in ascending column order
    float d0, d1, d2, d3;
    int   jl0 = tid, jl1 = tid + 128, jl2 = tid + 256, jl3 = tid + 384;

    if ((infoI & 63) != 63) {
        // ---------------- fast path: row has >=1 valid channel ----------------
        u64 ax2[CC], ay2[CC], az2[CC], aw2[CC];
#pragma unroll
        for (int c = 0; c < CC; c++) {
            float4 q1 = g_q1[c][base + qi];
            float4 q2 = g_q2[c][base + qi];
            float x = hi_ ? q1.y : q1.x;
            float y = hi_ ? q1.w : q1.z;
            float z = hi_ ? q2.y : q2.x;
            float w = hi_ ? q2.w : q2.z;
            ax2[c] = pack2(x, x);
            ay2[c] = pack2(y, y);
            az2[c] = pack2(z, z);
            aw2[c] = pack2(w, w);
        }
        const u64 neg2 = pack2(-2.0f, -2.0f);

#pragma unroll
        for (int p = 0; p < 2; p++) {
            const int q = tid + p * 128;
            float mdl[CC], mdh[CC];   // per-B-channel partial mins (short chains)
#pragma unroll
            for (int d = 0; d < CC; d++) {
                ulonglong2 vA = *reinterpret_cast<const ulonglong2*>(&g_q1[d][base + q]);
                ulonglong2 vB = *reinterpret_cast<const ulonglong2*>(&g_q2[d][base + q]);
                const u64 bx2 = vA.x, by2 = vA.y, bz2 = vB.x, bw2 = vB.y;
                float al, ah;
#pragma unroll
                for (int c = 0; c < CC; c++) {
                    // BIT-EXACT chain: dot = fma(ax,bx,fma(ay,by,az*bz));
                    // r = fma(-2, dot, aw+bw)
                    u64 t2 = mul2(az2[c], bz2);
                    t2 = fma2(ay2[c], by2, t2);
                    t2 = fma2(ax2[c], bx2, t2);
                    u64 s2 = add2(aw2[c], bw2);
                    u64 r2 = fma2(neg2, t2, s2);
                    float rl, rh; unpack2(r2, rl, rh);
                    if (c == 0) { al = rl; ah = rh; }
                    else        { al = fminf(al, rl); ah = fminf(ah, rh); }
                }
                mdl[d] = al; mdh[d] = ah;
            }
            // tree merge of 6 partials (min is exactly associative: same result)
            float mlo = fminf(fminf(fminf(mdl[0], mdl[1]), fminf(mdl[2], mdl[3])),
                              fminf(mdl[4], mdl[5]));
            float mhi = fminf(fminf(fminf(mdh[0], mdh[1]), fminf(mdh[2], mdh[3])),
                              fminf(mdh[4], mdh[5]));
            // sqrt & clamp hoisted out of the 36-way min (monotone)
            float dl = sqrtf(fmaxf(mlo, 0.0f));
            float dh = sqrtf(fmaxf(mhi, 0.0f));
            if (p == 0) { d0 = dl; d2 = dh; }   // cols tid, tid+256
            else        { d1 = dl; d3 = dh; }   // cols tid+128, tid+384
        }
    } else {
        // ---------------- cold fallback: row has no valid channel -------------
        // dist_j = 1e10 (BOS col) or 1e10 + sqrt(min_all d2); valid=0 always.
        float Ax[CC], Ay[CC], Az[CC], Asq[CC];
#pragma unroll
        for (int c = 0; c < CC; c++) {
            float4 q1 = g_q1[c][base + qi];
            float4 q2 = g_q2[c][base + qi];
            float x = hi_ ? q1.y : q1.x;
            float y = hi_ ? q1.w : q1.z;
            float z = hi_ ? q2.y : q2.x;
            Ax[c] = x; Ay[c] = y; Az[c] = z;
            Asq[c] = x * x + y * y + z * z;
        }
        float dv[4];
#pragma unroll
        for (int t = 0; t < 4; t++) {
            const int jl = tid + t * 128;          // ascending, matches jl0..jl3
            const int q  = jl & (HB - 1);
            const int hh = jl >> 8;
            const int j  = (b << 9) + jl;
            float dist;
            if (g_info[j] & 64) {
                dist = 1e10f;
            } else {
                float m = 3.4e38f;
#pragma unroll
                for (int d = 0; d < CC; d++) {
                    float4 q1 = g_q1[d][base + q];
                    float4 q2 = g_q2[d][base + q];
                    float bx = hh ? q1.y : q1.x;
                    float by = hh ? q1.w : q1.z;
                    float bz = hh ? q2.y : q2.x;
                    float bsq = bx * bx + by * by + bz * bz;
#pragma unroll
                    for (int c = 0; c < CC; c++) {
                        float dot = fmaf(Ax[c], bx, fmaf(Ay[c], by, Az[c] * bz));
                        float r = fmaf(-2.0f, dot, Asq[c] + bsq);
                        m = fminf(m, r);
                    }
                }
                dist = 1e10f + sqrtf(fmaxf(m, 0.0f));
            }
            dv[t] = dist;
        }
        d0 = dv[0]; d1 = dv[1]; d2 = dv[2]; d3 = dv[3];
    }

    // stable sort of 4 (dist, jl) candidates (strict >; equal keys never cross,
    // so ties stay in ascending-jl order)
#define CSWAP(da, db, ja, jb) { \
    if (da > db) { float tf = da; da = db; db = tf; int ti = ja; ja = jb; jb = ti; } }
    CSWAP(d0, d1, jl0, jl1) CSWAP(d2, d3, jl2, jl3)
    CSWAP(d0, d2, jl0, jl2) CSWAP(d1, d3, jl1, jl3)
    CSWAP(d1, d2, jl1, jl2)
#undef CSWAP

    // per-warp: 9 rounds of REDUX.MIN warp-min (dist bits are order-isomorphic
    // as u32 since dist >= 0) with exact lower-index tie-break.
    const int wid = tid >> 5;
    for (int r = 0; r < KK; r++) {
        unsigned db = __float_as_uint(d0);
        unsigned m  = __reduce_min_sync(0xFFFFFFFFu, db);
        unsigned cj = __reduce_min_sync(0xFFFFFFFFu,
                                        (db == m) ? (unsigned)jl0 : 0xFFFFFFFFu);
        if (db == m && (unsigned)jl0 == cj) {     // unique owner (jl unique)
            wOut[wid * KK + r] = ((u64)m << 32) | cj;
            // pop head (shift register; no dynamic indexing)
            d0 = d1; jl0 = jl1;
            d1 = d2; jl1 = jl2;
            d2 = d3; jl2 = jl3;
            d3 = INF;
        }
    }
    __syncthreads();

    // parallel rank-merge of 4 sorted 9-lists; ranks < 9 write outputs directly.
    // u64 keys carry (dist_bits, jl) so cross-warp ties also rank by lower jl.
    if (tid < 4 * KK) {
        const u64 key = wOut[tid];
        const int myw = tid / KK;
        int rank = tid - myw * KK;
#pragma unroll
        for (int w = 0; w < 4; w++) {
            if (w == myw) continue;
#pragma unroll
            for (int rr = 0; rr < KK; rr++)
                rank += (wOut[w * KK + rr] < key);
        }
        if (rank < KK) {
            float dd = __uint_as_float((unsigned)(key >> 32));
            int   jl = (int)(key & 0xFFFFFFFFu);
            int  dst = (b << 9) + jl;
            bool valid = (dd < 1e10f) && (sec[i] == sec[dst]);
            out[0 * NK + i * KK + rank] = dd;
            out[1 * NK + i * KK + rank] = (float)i;
            out[2 * NK + i * KK + rank] = valid ? (float)dst : -1.0f;
            out[3 * NK + i * KK + rank] = valid ? 1.0f : 0.0f;
        }
    }
}

// ---------------------------------------------------------------------------
extern "C" void kernel_launch(void* const* d_in, const int* in_sizes, int n_in,
                              void* d_out, int out_size) {
    const float* X   = (const float*)d_in[0];
    const int*   AP  = (const int*)d_in[1];
    const int*   S   = (const int*)d_in[2];
    const int*   sec = (const int*)d_in[3];
    float* out = (float*)d_out;

    prep_kernel<<<2 * NB, 128>>>(X, AP, S);
    knn_kernel<<<NN + EDGE_BLOCKS, 128>>>(sec, out);
}

// round 12
// speedup vs baseline: 1.4112x; 1.0702x over previous
#include <cuda_runtime.h>
#include <cstdint>

// Problem constants (fixed by reference setup_inputs)
#define NB  8
#define LSZ 512
#define CC  6
#define NN  (NB * LSZ)       // 4096
#define KK  9
#define NK  (NN * KK)        // 36864
#define HB  256              // half graph (column pairing distance)

#define GL_PER   (2 * LSZ - 1)
#define SQ_PER   (2 * (LSZ - 2))
#define GL_TOT   (NB * GL_PER)      // 8184
#define SQ_TOT   (NB * SQ_PER)      // 8160
#define EDGE_TOT (2 * GL_TOT + 2 * SQ_TOT)   // 32688
#define EDGE_BLOCKS ((EDGE_TOT + 127) / 128) // 256 CTAs of 128 appended to knn

typedef unsigned long long u64;

// Interleaved paired SoA per channel c, per (graph b, q in [0,256)):
//   g_q1[c][b*HB+q] = (x_lo, x_hi, y_lo, y_hi)
//   g_q2[c][b*HB+q] = (z_lo, z_hi, w_lo, w_hi)
// lo = node b*512+q, hi = node b*512+q+256.
// w = |x|^2, or 1e30 sentinel if channel padded OR node is BOS/global.
__device__ float4 g_q1[CC][NB * HB];
__device__ float4 g_q2[CC][NB * HB];
__device__ int    g_info[NN];   // bits 0..5: pad mask; bit 6: BOS/global

// ---- packed f32x2 helpers (each half rounds identically to scalar op) ----
__device__ __forceinline__ u64 pack2(float lo, float hi) {
    u64 r; asm("mov.b64 %0, {%1, %2};" : "=l"(r) : "f"(lo), "f"(hi)); return r;
}
__device__ __forceinline__ void unpack2(u64 v, float& lo, float& hi) {
    asm("mov.b64 {%0, %1}, %2;" : "=f"(lo), "=f"(hi) : "l"(v));
}
__device__ __forceinline__ u64 mul2(u64 a, u64 b) {
    u64 d; asm("mul.rn.f32x2 %0, %1, %2;" : "=l"(d) : "l"(a), "l"(b)); return d;
}
__device__ __forceinline__ u64 add2(u64 a, u64 b) {
    u64 d; asm("add.rn.f32x2 %0, %1, %2;" : "=l"(d) : "l"(a), "l"(b)); return d;
}
__device__ __forceinline__ u64 fma2(u64 a, u64 b, u64 c) {
    u64 d; asm("fma.rn.f32x2 %0, %1, %2, %3;" : "=l"(d) : "l"(a), "l"(b), "l"(c)); return d;
}

// ---------------------------------------------------------------------------
// Kernel 1: prep only (interleaved paired SoA + masks). 16 CTAs x 128.
// CTA (b, half): handles q in [half*128, half*128+128) of graph b.
// ---------------------------------------------------------------------------
__global__ void __launch_bounds__(128)
prep_kernel(const float* __restrict__ X,
            const int* __restrict__ AP,
            const int* __restrict__ S) {
    const int b = blockIdx.x >> 1;
    const int q = ((blockIdx.x & 1) << 7) + threadIdx.x;   // 0..255
    float ax[2][CC], ay[2][CC], az[2][CC], aw[2][CC];
#pragma unroll
    for (int h = 0; h < 2; h++) {
        const int i = b * LSZ + h * HB + q;
        const bool bos = (S[i] == 0);
        int mask = bos ? 64 : 0;
#pragma unroll
        for (int c = 0; c < CC; c++) {
            float x = X[(i * CC + c) * 3 + 0];
            float y = X[(i * CC + c) * 3 + 1];
            float z = X[(i * CC + c) * 3 + 2];
            float sq = x * x + y * y + z * z;
            bool pad = (AP[i * CC + c] == 0);
            if (pad) mask |= (1 << c);
            ax[h][c] = x; ay[h][c] = y; az[h][c] = z;
            aw[h][c] = (pad || bos) ? 1e30f : sq;
        }
        g_info[i] = mask;
    }
#pragma unroll
    for (int c = 0; c < CC; c++) {
        g_q1[c][b * HB + q] = make_float4(ax[0][c], ax[1][c], ay[0][c], ay[1][c]);
        g_q2[c][b * HB + q] = make_float4(az[0][c], az[1][c], aw[0][c], aw[1][c]);
    }
}

// ---------------------------------------------------------------------------
// Kernel 2: per-row masked min-pair distance (bit-exact) + top-9 with exact
// lower-index tie-break via REDUX.MIN. Blocks >= NN emit the static edge
// lists. One CTA per row; 128 threads; thread t owns columns t, t+128,
// t+256, t+384 (ascending for stable tie order), as two f32x2 column pairs.
// Min accumulation: 2 accumulators per half (exactly associative).
// __launch_bounds__(128, 8) pins 8 CTAs/SM (regs <= 64).
// ---------------------------------------------------------------------------
__global__ void __launch_bounds__(128, 8)
knn_kernel(const int* __restrict__ sec, float* __restrict__ out) {
    const int tid = threadIdx.x;

    // ---- tail CTAs: static global + sequential edge lists ----
    if (blockIdx.x >= NN) {
        const int t = (blockIdx.x - NN) * 128 + tid;
        if (t >= EDGE_TOT) return;
        int val;
        if (t < 2 * GL_TOT) {
            int r = t / GL_TOT, u = t % GL_TOT;
            int bb = u / GL_PER, q = u % GL_PER;
            if (r == 0) val = (q < LSZ) ? 0 : (q - (LSZ - 1));
            else        val = (q < LSZ) ? q : 0;
            val += bb * LSZ;
        } else {
            int t2 = t - 2 * GL_TOT;
            int r = t2 / SQ_TOT, u = t2 % SQ_TOT;
            int bb = u / SQ_PER, q = u % SQ_PER;
            if (r == 0) val = (q < LSZ - 2) ? (q + 1) : (q - (LSZ - 2) + 2);
            else        val = (q < LSZ - 2) ? (q + 2) : (q - (LSZ - 2) + 1);
            val += bb * LSZ;
        }
        out[4 * NK + t] = (float)val;
        return;
    }

    const int i = blockIdx.x;
    const int b = i >> 9;
    const float INF = __int_as_float(0x7f800000);

    __shared__ u64 wOut[4 * KK];

    const int infoI = g_info[i];

    // BOS/global row: entire dist row is 1e10 -> dknn=1e10, valid=0, dst=-1.
    if (infoI & 64) {
        if (tid < KK) {
            out[0 * NK + i * KK + tid] = 1e10f;
            out[1 * NK + i * KK + tid] = (float)i;
            out[2 * NK + i * KK + tid] = -1.0f;
            out[3 * NK + i * KK + tid] = 0.0f;
        }
        return;
    }

    const int base = b * HB;
    const int li   = i & (LSZ - 1);
    const int qi   = li & (HB - 1);
    const int hi_  = li >> 8;       // which half of the pair holds row i

    // per-thread candidates in ascending column order
    float d0, d1, d2, d3;
    int   jl0 = tid, jl1 = tid + 128, jl2 = tid + 256, jl3 = tid + 384;

    if ((infoI & 63) != 63) {
        // ---------------- fast path: row has >=1 valid channel ----------------
        u64 ax2[CC], ay2[CC], az2[CC], aw2[CC];
#pragma unroll
        for (int c = 0; c < CC; c++) {
            float4 q1 = g_q1[c][base + qi];
            float4 q2 = g_q2[c][base + qi];
            float x = hi_ ? q1.y : q1.x;
            float y = hi_ ? q1.w : q1.z;
            float z = hi_ ? q2.y : q2.x;
            float w = hi_ ? q2.w : q2.z;
            ax2[c] = pack2(x, x);
            ay2[c] = pack2(y, y);
            az2[c] = pack2(z, z);
            aw2[c] = pack2(w, w);
        }
        const u64 neg2 = pack2(-2.0f, -2.0f);

#pragma unroll
        for (int p = 0; p < 2; p++) {
            const int q = tid + p * 128;
            // two accumulators per half: chains of 18 instead of 36
            float mlo0 = 3.4e38f, mhi0 = 3.4e38f;
            float mlo1 = 3.4e38f, mhi1 = 3.4e38f;
#pragma unroll
            for (int d = 0; d < CC; d++) {
                ulonglong2 vA = *reinterpret_cast<const ulonglong2*>(&g_q1[d][base + q]);
                ulonglong2 vB = *reinterpret_cast<const ulonglong2*>(&g_q2[d][base + q]);
                const u64 bx2 = vA.x, by2 = vA.y, bz2 = vB.x, bw2 = vB.y;
#pragma unroll
                for (int c = 0; c < CC; c++) {
                    // BIT-EXACT chain: dot = fma(ax,bx,fma(ay,by,az*bz));
                    // r = fma(-2, dot, aw+bw)
                    u64 t2 = mul2(az2[c], bz2);
                    t2 = fma2(ay2[c], by2, t2);
                    t2 = fma2(ax2[c], bx2, t2);
                    u64 s2 = add2(aw2[c], bw2);
                    u64 r2 = fma2(neg2, t2, s2);
                    float rl, rh; unpack2(r2, rl, rh);
                    if (d < 3) { mlo0 = fminf(mlo0, rl); mhi0 = fminf(mhi0, rh); }
                    else       { mlo1 = fminf(mlo1, rl); mhi1 = fminf(mhi1, rh); }
                }
            }
            // merge (min exactly associative: identical result set)
            float mlo = fminf(mlo0, mlo1);
            float mhi = fminf(mhi0, mhi1);
            // sqrt & clamp hoisted out of the 36-way min (monotone)
            float dl = sqrtf(fmaxf(mlo, 0.0f));
            float dh = sqrtf(fmaxf(mhi, 0.0f));
            if (p == 0) { d0 = dl; d2 = dh; }   // cols tid, tid+256
            else        { d1 = dl; d3 = dh; }   // cols tid+128, tid+384
        }
    } else {
        // ---------------- cold fallback: row has no valid channel -------------
        // dist_j = 1e10 (BOS col) or 1e10 + sqrt(min_all d2); valid=0 always.
        float Ax[CC], Ay[CC], Az[CC], Asq[CC];
#pragma unroll
        for (int c = 0; c < CC; c++) {
            float4 q1 = g_q1[c][base + qi];
            float4 q2 = g_q2[c][base + qi];
            float x = hi_ ? q1.y : q1.x;
            float y = hi_ ? q1.w : q1.z;
            float z = hi_ ? q2.y : q2.x;
            Ax[c] = x; Ay[c] = y; Az[c] = z;
            Asq[c] = x * x + y * y + z * z;
        }
        float dv[4];
#pragma unroll
        for (int t = 0; t < 4; t++) {
            const int jl = tid + t * 128;          // ascending, matches jl0..jl3
            const int q  = jl & (HB - 1);
            const int hh = jl >> 8;
            const int j  = (b << 9) + jl;
            float dist;
            if (g_info[j] & 64) {
                dist = 1e10f;
            } else {
                float m = 3.4e38f;
#pragma unroll
                for (int d = 0; d < CC; d++) {
                    float4 q1 = g_q1[d][base + q];
                    float4 q2 = g_q2[d][base + q];
                    float bx = hh ? q1.y : q1.x;
                    float by = hh ? q1.w : q1.z;
                    float bz = hh ? q2.y : q2.x;
                    float bsq = bx * bx + by * by + bz * bz;
#pragma unroll
                    for (int c = 0; c < CC; c++) {
                        float dot = fmaf(Ax[c], bx, fmaf(Ay[c], by, Az[c] * bz));
                        float r = fmaf(-2.0f, dot, Asq[c] + bsq);
                        m = fminf(m, r);
                    }
                }
                dist = 1e10f + sqrtf(fmaxf(m, 0.0f));
            }
            dv[t] = dist;
        }
        d0 = dv[0]; d1 = dv[1]; d2 = dv[2]; d3 = dv[3];
    }

    // stable sort of 4 (dist, jl) candidates (strict >; equal keys never cross,
    // so ties stay in ascending-jl order)
#define CSWAP(da, db, ja, jb) { \
    if (da > db) { float tf = da; da = db; db = tf; int ti = ja; ja = jb; jb = ti; } }
    CSWAP(d0, d1, jl0, jl1) CSWAP(d2, d3, jl2, jl3)
    CSWAP(d0, d2, jl0, jl2) CSWAP(d1, d3, jl1, jl3)
    CSWAP(d1, d2, jl1, jl2)
#undef CSWAP

    // per-warp: 9 rounds of REDUX.MIN warp-min (dist bits are order-isomorphic
    // as u32 since dist >= 0) with exact lower-index tie-break.
    const int wid = tid >> 5;
    for (int r = 0; r < KK; r++) {
        unsigned db = __float_as_uint(d0);
        unsigned m  = __reduce_min_sync(0xFFFFFFFFu, db);
        unsigned cj = __reduce_min_sync(0xFFFFFFFFu,
                                        (db == m) ? (unsigned)jl0 : 0xFFFFFFFFu);
        if (db == m && (unsigned)jl0 == cj) {     // unique owner (jl unique)
            wOut[wid * KK + r] = ((u64)m << 32) | cj;
            // pop head (shift register; no dynamic indexing)
            d0 = d1; jl0 = jl1;
            d1 = d2; jl1 = jl2;
            d2 = d3; jl2 = jl3;
            d3 = INF;
        }
    }
    __syncthreads();

    // parallel rank-merge of 4 sorted 9-lists; ranks < 9 write outputs directly.
    // u64 keys carry (dist_bits, jl) so cross-warp ties also rank by lower jl.
    if (tid < 4 * KK) {
        const u64 key = wOut[tid];
        const int myw = tid / KK;
        int rank = tid - myw * KK;
#pragma unroll
        for (int w = 0; w < 4; w++) {
            if (w == myw) continue;
#pragma unroll
            for (int rr = 0; rr < KK; rr++)
                rank += (wOut[w * KK + rr] < key);
        }
        if (rank < KK) {
            float dd = __uint_as_float((unsigned)(key >> 32));
            int   jl = (int)(key & 0xFFFFFFFFu);
            int  dst = (b << 9) + jl;
            bool valid = (dd < 1e10f) && (sec[i] == sec[dst]);
            out[0 * NK + i * KK + rank] = dd;
            out[1 * NK + i * KK + rank] = (float)i;
            out[2 * NK + i * KK + rank] = valid ? (float)dst : -1.0f;
            out[3 * NK + i * KK + rank] = valid ? 1.0f : 0.0f;
        }
    }
}

// ---------------------------------------------------------------------------
extern "C" void kernel_launch(void* const* d_in, const int* in_sizes, int n_in,
                              void* d_out, int out_size) {
    const float* X   = (const float*)d_in[0];
    const int*   AP  = (const int*)d_in[1];
    const int*   S   = (const int*)d_in[2];
    const int*   sec = (const int*)d_in[3];
    float* out = (float*)d_out;

    prep_kernel<<<2 * NB, 128>>>(X, AP, S);
    knn_kernel<<<NN + EDGE_BLOCKS, 128>>>(sec, out);
}

// round 14
// speedup vs baseline: 1.4127x; 1.0011x over previous
#include <cuda_runtime.h>
#include <cstdint>

// Problem constants (fixed by reference setup_inputs)
#define NB  8
#define LSZ 512
#define CC  6
#define NN  (NB * LSZ)       // 4096
#define KK  9
#define NK  (NN * KK)        // 36864
#define HB  256              // half graph (column pairing distance)
#define GHB (NB * HB)        // 2048 pair-slots total

#define GL_PER   (2 * LSZ - 1)
#define SQ_PER   (2 * (LSZ - 2))
#define GL_TOT   (NB * GL_PER)      // 8184
#define SQ_TOT   (NB * SQ_PER)      // 8160
#define EDGE_TOT (2 * GL_TOT + 2 * SQ_TOT)   // 32688
#define EDGE_BLOCKS ((EDGE_TOT + 127) / 128) // 256 CTAs of 128 appended to knn

typedef unsigned long long u64;

// Single fused paired-SoA array. Slot layout:
//   g_pair[(c*2+0)*GHB + b*HB + q] = (x_lo, x_hi, y_lo, y_hi)   ("q1" of channel c)
//   g_pair[(c*2+1)*GHB + b*HB + q] = (z_lo, z_hi, w_lo, w_hi)   ("q2" of channel c)
// lo = node b*512+q, hi = node b*512+q+256.
// w = |x|^2, or 1e30 sentinel if channel padded OR node is BOS/global.
// One base address per q; all 12 channel planes are reachable via constant
// byte offsets (plane stride = GHB*16 = 32768 B) -> immediate-offset LDG.128.
__device__ float4 g_pair[CC * 2 * GHB];
__device__ int    g_info[NN];   // bits 0..5: pad mask; bit 6: BOS/global

// ---- packed f32x2 helpers (each half rounds identically to scalar op) ----
__device__ __forceinline__ u64 pack2(float lo, float hi) {
    u64 r; asm("mov.b64 %0, {%1, %2};" : "=l"(r) : "f"(lo), "f"(hi)); return r;
}
__device__ __forceinline__ void unpack2(u64 v, float& lo, float& hi) {
    asm("mov.b64 {%0, %1}, %2;" : "=f"(lo), "=f"(hi) : "l"(v));
}
__device__ __forceinline__ u64 mul2(u64 a, u64 b) {
    u64 d; asm("mul.rn.f32x2 %0, %1, %2;" : "=l"(d) : "l"(a), "l"(b)); return d;
}
__device__ __forceinline__ u64 add2(u64 a, u64 b) {
    u64 d; asm("add.rn.f32x2 %0, %1, %2;" : "=l"(d) : "l"(a), "l"(b)); return d;
}
__device__ __forceinline__ u64 fma2(u64 a, u64 b, u64 c) {
    u64 d; asm("fma.rn.f32x2 %0, %1, %2, %3;" : "=l"(d) : "l"(a), "l"(b), "l"(c)); return d;
}

// ---------------------------------------------------------------------------
// Kernel 1: prep only (fused paired SoA + masks). 16 CTAs x 128.
// CTA (b, half): handles q in [half*128, half*128+128) of graph b.
// ---------------------------------------------------------------------------
__global__ void __launch_bounds__(128)
prep_kernel(const float* __restrict__ X,
            const int* __restrict__ AP,
            const int* __restrict__ S) {
    const int b = blockIdx.x >> 1;
    const int q = ((blockIdx.x & 1) << 7) + threadIdx.x;   // 0..255
    float ax[2][CC], ay[2][CC], az[2][CC], aw[2][CC];
#pragma unroll
    for (int h = 0; h < 2; h++) {
        const int i = b * LSZ + h * HB + q;
        const bool bos = (S[i] == 0);
        int mask = bos ? 64 : 0;
#pragma unroll
        for (int c = 0; c < CC; c++) {
            float x = X[(i * CC + c) * 3 + 0];
            float y = X[(i * CC + c) * 3 + 1];
            float z = X[(i * CC + c) * 3 + 2];
            float sq = x * x + y * y + z * z;
            bool pad = (AP[i * CC + c] == 0);
            if (pad) mask |= (1 << c);
            ax[h][c] = x; ay[h][c] = y; az[h][c] = z;
            aw[h][c] = (pad || bos) ? 1e30f : sq;
        }
        g_info[i] = mask;
    }
    const int slot = b * HB + q;
#pragma unroll
    for (int c = 0; c < CC; c++) {
        g_pair[(c * 2 + 0) * GHB + slot] = make_float4(ax[0][c], ax[1][c], ay[0][c], ay[1][c]);
        g_pair[(c * 2 + 1) * GHB + slot] = make_float4(az[0][c], az[1][c], aw[0][c], aw[1][c]);
    }
}

// ---------------------------------------------------------------------------
// Kernel 2: per-row masked min-pair distance (bit-exact) + top-9 with exact
// lower-index tie-break via REDUX.MIN. Blocks >= NN emit the static edge
// lists. One CTA per row; 128 threads; thread t owns columns t, t+128,
// t+256, t+384 (ascending for stable tie order), as two f32x2 column pairs.
// Min accumulation: scalar fminf, 2 accumulators per half (exactly assoc.).
// __launch_bounds__(128, 8) pins 8 CTAs/SM (regs <= 64).
// ---------------------------------------------------------------------------
__global__ void __launch_bounds__(128, 8)
knn_kernel(const int* __restrict__ sec, float* __restrict__ out) {
    const int tid = threadIdx.x;

    // ---- tail CTAs: static global + sequential edge lists ----
    if (blockIdx.x >= NN) {
        const int t = (blockIdx.x - NN) * 128 + tid;
        if (t >= EDGE_TOT) return;
        int val;
        if (t < 2 * GL_TOT) {
            int r = t / GL_TOT, u = t % GL_TOT;
            int bb = u / GL_PER, q = u % GL_PER;
            if (r == 0) val = (q < LSZ) ? 0 : (q - (LSZ - 1));
            else        val = (q < LSZ) ? q : 0;
            val += bb * LSZ;
        } else {
            int t2 = t - 2 * GL_TOT;
            int r = t2 / SQ_TOT, u = t2 % SQ_TOT;
            int bb = u / SQ_PER, q = u % SQ_PER;
            if (r == 0) val = (q < LSZ - 2) ? (q + 1) : (q - (LSZ - 2) + 2);
            else        val = (q < LSZ - 2) ? (q + 2) : (q - (LSZ - 2) + 1);
            val += bb * LSZ;
        }
        out[4 * NK + t] = (float)val;
        return;
    }

    const int i = blockIdx.x;
    const int b = i >> 9;
    const float INF = __int_as_float(0x7f800000);

    __shared__ u64 wOut[4 * KK];

    const int infoI = g_info[i];

    // BOS/global row: entire dist row is 1e10 -> dknn=1e10, valid=0, dst=-1.
    if (infoI & 64) {
        if (tid < KK) {
            out[0 * NK + i * KK + tid] = 1e10f;
            out[1 * NK + i * KK + tid] = (float)i;
            out[2 * NK + i * KK + tid] = -1.0f;
            out[3 * NK + i * KK + tid] = 0.0f;
        }
        return;
    }

    const int base = b * HB;
    const int li   = i & (LSZ - 1);
    const int qi   = li & (HB - 1);
    const int hi_  = li >> 8;       // which half of the pair holds row i

    // per-thread candidates in ascending column order
    float d0, d1, d2, d3;
    int   jl0 = tid, jl1 = tid + 128, jl2 = tid + 256, jl3 = tid + 384;

    if ((infoI & 63) != 63) {
        // ---------------- fast path: row has >=1 valid channel ----------------
        u64 ax2[CC], ay2[CC], az2[CC], aw2[CC];
        {
            const float4* pa = &g_pair[base + qi];
#pragma unroll
            for (int c = 0; c < CC; c++) {
                float4 q1 = pa[(c * 2 + 0) * GHB];
                float4 q2 = pa[(c * 2 + 1) * GHB];
                float x = hi_ ? q1.y : q1.x;
                float y = hi_ ? q1.w : q1.z;
                float z = hi_ ? q2.y : q2.x;
                float w = hi_ ? q2.w : q2.z;
                ax2[c] = pack2(x, x);
                ay2[c] = pack2(y, y);
                az2[c] = pack2(z, z);
                aw2[c] = pack2(w, w);
            }
        }
        const u64 neg2 = pack2(-2.0f, -2.0f);

#pragma unroll
        for (int p = 0; p < 2; p++) {
            const float4* pb = &g_pair[base + tid + p * 128];
            // two accumulators per half: chains of 18 instead of 36
            float mlo0 = 3.4e38f, mhi0 = 3.4e38f;
            float mlo1 = 3.4e38f, mhi1 = 3.4e38f;
#pragma unroll
            for (int d = 0; d < CC; d++) {
                ulonglong2 vA = *reinterpret_cast<const ulonglong2*>(pb + (d * 2 + 0) * GHB);
                ulonglong2 vB = *reinterpret_cast<const ulonglong2*>(pb + (d * 2 + 1) * GHB);
                const u64 bx2 = vA.x, by2 = vA.y, bz2 = vB.x, bw2 = vB.y;
#pragma unroll
                for (int c = 0; c < CC; c++) {
                    // BIT-EXACT chain: dot = fma(ax,bx,fma(ay,by,az*bz));
                    // r = fma(-2, dot, aw+bw)
                    u64 t2 = mul2(az2[c], bz2);
                    t2 = fma2(ay2[c], by2, t2);
                    t2 = fma2(ax2[c], bx2, t2);
                    u64 s2 = add2(aw2[c], bw2);
                    u64 r2 = fma2(neg2, t2, s2);
                    float rl, rh; unpack2(r2, rl, rh);
                    if (d < 3) { mlo0 = fminf(mlo0, rl); mhi0 = fminf(mhi0, rh); }
                    else       { mlo1 = fminf(mlo1, rl); mhi1 = fminf(mhi1, rh); }
                }
            }
            // merge (min exactly associative: identical result set)
            float mlo = fminf(mlo0, mlo1);
            float mhi = fminf(mhi0, mhi1);
            // sqrt & clamp hoisted out of the 36-way min (monotone)
            float dl = sqrtf(fmaxf(mlo, 0.0f));
            float dh = sqrtf(fmaxf(mhi, 0.0f));
            if (p == 0) { d0 = dl; d2 = dh; }   // cols tid, tid+256
            else        { d1 = dl; d3 = dh; }   // cols tid+128, tid+384
        }
    } else {
        // ---------------- cold fallback: row has no valid channel -------------
        // dist_j = 1e10 (BOS col) or 1e10 + sqrt(min_all d2); valid=0 always.
        float Ax[CC], Ay[CC], Az[CC], Asq[CC];
        {
            const float4* pa = &g_pair[base + qi];
#pragma unroll
            for (int c = 0; c < CC; c++) {
                float4 q1 = pa[(c * 2 + 0) * GHB];
                float4 q2 = pa[(c * 2 + 1) * GHB];
                float x = hi_ ? q1.y : q1.x;
                float y = hi_ ? q1.w : q1.z;
                float z = hi_ ? q2.y : q2.x;
                Ax[c] = x; Ay[c] = y; Az[c] = z;
                Asq[c] = x * x + y * y + z * z;
            }
        }
        float dv[4];
#pragma unroll
        for (int t = 0; t < 4; t++) {
            const int jl = tid + t * 128;          // ascending, matches jl0..jl3
            const int q  = jl & (HB - 1);
            const int hh = jl >> 8;
            const int j  = (b << 9) + jl;
            float dist;
            if (g_info[j] & 64) {
                dist = 1e10f;
            } else {
                const float4* pb = &g_pair[base + q];
                float m = 3.4e38f;
#pragma unroll
                for (int d = 0; d < CC; d++) {
                    float4 q1 = pb[(d * 2 + 0) * GHB];
                    float4 q2 = pb[(d * 2 + 1) * GHB];
                    float bx = hh ? q1.y : q1.x;
                    float by = hh ? q1.w : q1.z;
                    float bz = hh ? q2.y : q2.x;
                    float bsq = bx * bx + by * by + bz * bz;
#pragma unroll
                    for (int c = 0; c < CC; c++) {
                        float dot = fmaf(Ax[c], bx, fmaf(Ay[c], by, Az[c] * bz));
                        float r = fmaf(-2.0f, dot, Asq[c] + bsq);
                        m = fminf(m, r);
                    }
                }
                dist = 1e10f + sqrtf(fmaxf(m, 0.0f));
            }
            dv[t] = dist;
        }
        d0 = dv[0]; d1 = dv[1]; d2 = dv[2]; d3 = dv[3];
    }

    // stable sort of 4 (dist, jl) candidates (strict >; equal keys never cross,
    // so ties stay in ascending-jl order)
#define CSWAP(da, db, ja, jb) { \
    if (da > db) { float tf = da; da = db; db = tf; int ti = ja; ja = jb; jb = ti; } }
    CSWAP(d0, d1, jl0, jl1) CSWAP(d2, d3, jl2, jl3)
    CSWAP(d0, d2, jl0, jl2) CSWAP(d1, d3, jl1, jl3)
    CSWAP(d1, d2, jl1, jl2)
#undef CSWAP

    // per-warp: 9 rounds of REDUX.MIN warp-min (dist bits are order-isomorphic
    // as u32 since dist >= 0) with exact lower-index tie-break.
    const int wid = tid >> 5;
    for (int r = 0; r < KK; r++) {
        unsigned db = __float_as_uint(d0);
        unsigned m  = __reduce_min_sync(0xFFFFFFFFu, db);
        unsigned cj = __reduce_min_sync(0xFFFFFFFFu,
                                        (db == m) ? (unsigned)jl0 : 0xFFFFFFFFu);
        if (db == m && (unsigned)jl0 == cj) {     // unique owner (jl unique)
            wOut[wid * KK + r] = ((u64)m << 32) | cj;
            // pop head (shift register; no dynamic indexing)
            d0 = d1; jl0 = jl1;
            d1 = d2; jl1 = jl2;
            d2 = d3; jl2 = jl3;
            d3 = INF;
        }
    }
    __syncthreads();

    // parallel rank-merge of 4 sorted 9-lists; ranks < 9 write outputs directly.
    // u64 keys carry (dist_bits, jl) so cross-warp ties also rank by lower jl.
    if (tid < 4 * KK) {
        const u64 key = wOut[tid];
        const int myw = tid / KK;
        int rank = tid - myw * KK;
#pragma unroll
        for (int w = 0; w < 4; w++) {
            if (w == myw) continue;
#pragma unroll
            for (int rr = 0; rr < KK; rr++)
                rank += (wOut[w * KK + rr] < key);
        }
        if (rank < KK) {
            float dd = __uint_as_float((unsigned)(key >> 32));
            int   jl = (int)(key & 0xFFFFFFFFu);
            int  dst = (b << 9) + jl;
            bool valid = (dd < 1e10f) && (sec[i] == sec[dst]);
            out[0 * NK + i * KK + rank] = dd;
            out[1 * NK + i * KK + rank] = (float)i;
            out[2 * NK + i * KK + rank] = valid ? (float)dst : -1.0f;
            out[3 * NK + i * KK + rank] = valid ? 1.0f : 0.0f;
        }
    }
}

// ---------------------------------------------------------------------------
extern "C" void kernel_launch(void* const* d_in, const int* in_sizes, int n_in,
                              void* d_out, int out_size) {
    const float* X   = (const float*)d_in[0];
    const int*   AP  = (const int*)d_in[1];
    const int*   S   = (const int*)d_in[2];
    const int*   sec = (const int*)d_in[3];
    float* out = (float*)d_out;

    prep_kernel<<<2 * NB, 128>>>(X, AP, S);
    knn_kernel<<<NN + EDGE_BLOCKS, 128>>>(sec, out);
}